// round 9
// baseline (speedup 1.0000x reference)
#include <cuda_runtime.h>
#include <cuda_bf16.h>
#include <cstdint>
#include <stdint.h>
#include <math.h>

// Problem constants
#define Dd 1024   // feature dim
#define Cc 1000   // prototypes
#define Bb 128    // batch
#define RT 1128   // Cc + Bb stacked rows
#define MP 1152   // RT padded to multiple of 64
#define KS 8      // split-K for cross-dot gemm
#define KC (Dd / KS)
#define NB 148    // persistent grid size (<= SM count, all co-resident)

// Scratch (device globals — no allocation allowed)
__device__ __nv_bfloat16 g_Abf[MP * Dd];   // [mu; x; 0] bf16
__device__ __nv_bfloat16 g_Bbf[Dd * Dd];   // tril(L)^T bf16 [n][k]
__device__ __nv_bfloat16 g_MAbf[MP * Dd];  // MA = [mu;x] @ tril(L)
__device__ float g_q[MP];                  // ||MA_r||^2 + 1e-6||in_r||^2
__device__ float g_bd[RT];                 // beta . in_r
__device__ float g_part[KS * Bb * Dd];     // per-z cross-dot slices
__device__ int   g_barCnt;                 // grid barrier counter (self-resetting)

// ---------------------------------------------------------------------------
// helpers
// ---------------------------------------------------------------------------
__device__ __forceinline__ void ldsm_x4(uint32_t* r, uint32_t addr) {
    asm volatile("ldmatrix.sync.aligned.m8n8.x4.shared.b16 {%0,%1,%2,%3}, [%4];\n"
                 : "=r"(r[0]), "=r"(r[1]), "=r"(r[2]), "=r"(r[3]) : "r"(addr));
}

__device__ __forceinline__ void mma_bf16(float* d, const uint32_t* a,
                                         uint32_t b0, uint32_t b1) {
    asm volatile(
        "mma.sync.aligned.m16n8k16.row.col.f32.bf16.bf16.f32 "
        "{%0,%1,%2,%3}, {%4,%5,%6,%7}, {%8,%9}, {%0,%1,%2,%3};\n"
        : "+f"(d[0]), "+f"(d[1]), "+f"(d[2]), "+f"(d[3])
        : "r"(a[0]), "r"(a[1]), "r"(a[2]), "r"(a[3]), "r"(b0), "r"(b1));
}

// Grid-wide barrier: all NB blocks co-resident (grid == NB <= #SM, 1 CTA/SM).
__device__ __forceinline__ void gridbar(int target) {
    __threadfence();
    __syncthreads();
    if (threadIdx.x == 0) {
        atomicAdd(&g_barCnt, 1);
        while (*(volatile int*)&g_barCnt < target) __nanosleep(64);
    }
    __syncthreads();
}

// ---------------------------------------------------------------------------
// Persistent mega-kernel
// ---------------------------------------------------------------------------
__global__ __launch_bounds__(256) void mega(const float* __restrict__ x,
                                            const float* __restrict__ mu,
                                            const float* __restrict__ beta,
                                            const float* __restrict__ L,
                                            const float* __restrict__ lmbda,
                                            const float* __restrict__ scale,
                                            float* __restrict__ out) {
    __shared__ __align__(16) __nv_bfloat16 As[64][40];
    __shared__ __align__(16) __nv_bfloat16 Bs[64][40];
    __shared__ float redf[2][8];

    int bid = blockIdx.x;
    int tid = threadIdx.x;
    int lane = tid & 31, w = tid >> 5;

    // ===================== P0: prep =====================
    // units [0, MP): convert row of [mu;x;0] + input stats
    // units [MP, MP+1024): tril+transpose 32x32 tile of L
    for (int u = bid; u < MP + 1024; u += NB) {
        __syncthreads();  // shared reuse across iterations
        if (u < MP) {
            int r = u;
            int k = tid * 4;
            float4 v = make_float4(0.f, 0.f, 0.f, 0.f);
            if (r < Cc)      v = *reinterpret_cast<const float4*>(mu + (size_t)r * Dd + k);
            else if (r < RT) v = *reinterpret_cast<const float4*>(x + (size_t)(r - Cc) * Dd + k);
            __nv_bfloat162 p0 = __floats2bfloat162_rn(v.x, v.y);
            __nv_bfloat162 p1 = __floats2bfloat162_rn(v.z, v.w);
            uint2 o;
            o.x = *reinterpret_cast<uint32_t*>(&p0);
            o.y = *reinterpret_cast<uint32_t*>(&p1);
            *reinterpret_cast<uint2*>(g_Abf + (size_t)r * Dd + k) = o;

            if (r < RT) {
                float4 b4 = *reinterpret_cast<const float4*>(beta + k);
                float sin_ = v.x * v.x + v.y * v.y + v.z * v.z + v.w * v.w;
                float sb = b4.x * v.x + b4.y * v.y + b4.z * v.z + b4.w * v.w;
#pragma unroll
                for (int off = 16; off > 0; off >>= 1) {
                    sin_ += __shfl_xor_sync(0xFFFFFFFFu, sin_, off);
                    sb += __shfl_xor_sync(0xFFFFFFFFu, sb, off);
                }
                if (lane == 0) { redf[0][w] = sin_; redf[1][w] = sb; }
                __syncthreads();
                if (tid == 0) {
                    float t0 = 0.f, t1 = 0.f;
#pragma unroll
                    for (int wq = 0; wq < 8; wq++) { t0 += redf[0][wq]; t1 += redf[1][wq]; }
                    g_q[r] = 1e-6f * t0;  // seed; gemm epilogue atomically adds ||MA||^2
                    g_bd[r] = t1;
                }
            } else if (tid == 0) {
                g_q[r] = 0.f;
            }
        } else {
            // tril + transpose one 32x32 tile of L (reuse As as float scratch)
            int tileId = u - MP;
            int bx = (tileId & 31) * 32;   // k base
            int by = (tileId >> 5) * 32;   // n base
            float* tf = reinterpret_cast<float*>(&As[0][0]);  // 32*33 floats fit
            int tx = tid & 31, ty = tid >> 5;
#pragma unroll
            for (int i = ty; i < 32; i += 8)
                tf[i * 33 + tx] = L[(size_t)(bx + i) * Dd + by + tx];
            __syncthreads();
#pragma unroll
            for (int i = ty; i < 32; i += 8) {
                int n = by + i, k = bx + tx;
                float v = (k >= n) ? tf[tx * 33 + i] : 0.f;
                g_Bbf[(size_t)n * Dd + k] = __float2bfloat16(v);
            }
        }
    }
    gridbar(NB);

    // ===================== P1: MA gemm =====================
    // 288 tiles (18 m x 16 n), 64x64, triangular K-skip. LPT pairing:
    // block bid (<144) does tiles {bid, 287-bid} -> near-constant work.
    {
        int wm = (w & 1) * 32, wn = (w >> 1) * 16;
        uint32_t aA[2], bA;
#pragma unroll
        for (int t2 = 0; t2 < 2; t2++)
            aA[t2] = (uint32_t)__cvta_generic_to_shared(
                &As[wm + t2 * 16 + (lane & 15)][(lane >> 4) * 8]);
        bA = (uint32_t)__cvta_generic_to_shared(
            &Bs[wn + (lane & 15)][(lane >> 4) * 8]);
        int arow = tid >> 2, acol = (tid & 3) * 8;

        for (int which = 0; which < 2 && bid < 144; which++) {
            int t = which ? (287 - bid) : bid;
            int bn = (t / 18) * 64;
            int bm = (t % 18) * 64;
            const __nv_bfloat16* aptr = g_Abf + (size_t)(bm + arow) * Dd + acol;
            const __nv_bfloat16* bptr = g_Bbf + (size_t)(bn + arow) * Dd + acol;

            float acc[2][2][4];
#pragma unroll
            for (int mt = 0; mt < 2; mt++)
#pragma unroll
                for (int nt = 0; nt < 2; nt++)
#pragma unroll
                    for (int e = 0; e < 4; e++) acc[mt][nt][e] = 0.f;

            int kstart = bn;  // tril: L^T[n][k]=0 for k<n
            uint4 pa = *reinterpret_cast<const uint4*>(aptr + kstart);
            uint4 pb = *reinterpret_cast<const uint4*>(bptr + kstart);

            for (int k0 = kstart; k0 < Dd; k0 += 32) {
                __syncthreads();
                *reinterpret_cast<uint4*>(&As[arow][acol]) = pa;
                *reinterpret_cast<uint4*>(&Bs[arow][acol]) = pb;
                __syncthreads();
                if (k0 + 32 < Dd) {
                    pa = *reinterpret_cast<const uint4*>(aptr + k0 + 32);
                    pb = *reinterpret_cast<const uint4*>(bptr + k0 + 32);
                }
#pragma unroll
                for (int ks = 0; ks < 2; ks++) {
                    uint32_t off = (uint32_t)(ks * 32);
                    uint32_t a0[4], a1[4], br[4];
                    ldsm_x4(a0, aA[0] + off);
                    ldsm_x4(a1, aA[1] + off);
                    ldsm_x4(br, bA + off);
                    mma_bf16(acc[0][0], a0, br[0], br[2]);
                    mma_bf16(acc[0][1], a0, br[1], br[3]);
                    mma_bf16(acc[1][0], a1, br[0], br[2]);
                    mma_bf16(acc[1][1], a1, br[1], br[3]);
                }
            }

            int mrow = lane >> 2;
            int ncol = (lane & 3) * 2;
#pragma unroll
            for (int mt = 0; mt < 2; mt++) {
                float s0 = 0.f, s1 = 0.f;
                int row = bm + wm + mt * 16 + mrow;
#pragma unroll
                for (int nt = 0; nt < 2; nt++) {
                    int col = bn + wn + nt * 8 + ncol;
                    __nv_bfloat162 lo = __floats2bfloat162_rn(acc[mt][nt][0], acc[mt][nt][1]);
                    __nv_bfloat162 hi = __floats2bfloat162_rn(acc[mt][nt][2], acc[mt][nt][3]);
                    *reinterpret_cast<__nv_bfloat162*>(g_MAbf + (size_t)row * Dd + col) = lo;
                    *reinterpret_cast<__nv_bfloat162*>(g_MAbf + (size_t)(row + 8) * Dd + col) = hi;
                    float l0 = __bfloat162float(lo.x), l1 = __bfloat162float(lo.y);
                    float h0 = __bfloat162float(hi.x), h1 = __bfloat162float(hi.y);
                    s0 += l0 * l0 + l1 * l1;
                    s1 += h0 * h0 + h1 * h1;
                }
                s0 += __shfl_xor_sync(0xFFFFFFFFu, s0, 1);
                s0 += __shfl_xor_sync(0xFFFFFFFFu, s0, 2);
                s1 += __shfl_xor_sync(0xFFFFFFFFu, s1, 1);
                s1 += __shfl_xor_sync(0xFFFFFFFFu, s1, 2);
                if ((lane & 3) == 0) {
                    atomicAdd(&g_q[row], s0);
                    atomicAdd(&g_q[row + 8], s1);
                }
            }
        }
    }
    gridbar(2 * NB);

    // ===================== P2: cross-dot gemm =====================
    // 256 tiles: bm(2) x bn(16) x z(8), each 64x64 over K-chunk of 128.
    // Direct stores into per-z slices of g_part (no atomics, no zeroing).
    {
        int wm = (w & 1) * 32, wn = (w >> 1) * 16;
        uint32_t aA[2], bA;
#pragma unroll
        for (int t2 = 0; t2 < 2; t2++)
            aA[t2] = (uint32_t)__cvta_generic_to_shared(
                &As[wm + t2 * 16 + (lane & 15)][(lane >> 4) * 8]);
        bA = (uint32_t)__cvta_generic_to_shared(
            &Bs[wn + (lane & 15)][(lane >> 4) * 8]);
        int arow = tid >> 2, acol = (tid & 3) * 8;

        for (int t = bid; t < 256; t += NB) {
            int bm = (t & 1) * 64;
            int bn = ((t >> 1) & 15) * 64;
            int z = t >> 5;
            int kb = z * KC;
            const __nv_bfloat16* aptr = g_MAbf + (size_t)(Cc + bm + arow) * Dd + kb + acol;
            const __nv_bfloat16* bptr = g_MAbf + (size_t)(bn + arow) * Dd + kb + acol;

            float acc[2][2][4];
#pragma unroll
            for (int mt = 0; mt < 2; mt++)
#pragma unroll
                for (int nt = 0; nt < 2; nt++)
#pragma unroll
                    for (int e = 0; e < 4; e++) acc[mt][nt][e] = 0.f;

            uint4 pa = *reinterpret_cast<const uint4*>(aptr);
            uint4 pb = *reinterpret_cast<const uint4*>(bptr);

#pragma unroll 1
            for (int k0 = 0; k0 < KC; k0 += 32) {
                __syncthreads();
                *reinterpret_cast<uint4*>(&As[arow][acol]) = pa;
                *reinterpret_cast<uint4*>(&Bs[arow][acol]) = pb;
                __syncthreads();
                if (k0 + 32 < KC) {
                    pa = *reinterpret_cast<const uint4*>(aptr + k0 + 32);
                    pb = *reinterpret_cast<const uint4*>(bptr + k0 + 32);
                }
#pragma unroll
                for (int ks = 0; ks < 2; ks++) {
                    uint32_t off = (uint32_t)(ks * 32);
                    uint32_t a0[4], a1[4], br[4];
                    ldsm_x4(a0, aA[0] + off);
                    ldsm_x4(a1, aA[1] + off);
                    ldsm_x4(br, bA + off);
                    mma_bf16(acc[0][0], a0, br[0], br[2]);
                    mma_bf16(acc[0][1], a0, br[1], br[3]);
                    mma_bf16(acc[1][0], a1, br[0], br[2]);
                    mma_bf16(acc[1][1], a1, br[1], br[3]);
                }
            }

            int mrow = lane >> 2;
            int ncol = (lane & 3) * 2;
            float* outz = g_part + (size_t)z * Bb * Dd;
#pragma unroll
            for (int mt = 0; mt < 2; mt++)
#pragma unroll
                for (int nt = 0; nt < 2; nt++) {
                    int row = bm + wm + mt * 16 + mrow;
                    int col = bn + wn + nt * 8 + ncol;
                    *reinterpret_cast<float2*>(outz + (size_t)row * Dd + col) =
                        make_float2(acc[mt][nt][0], acc[mt][nt][1]);
                    *reinterpret_cast<float2*>(outz + (size_t)(row + 8) * Dd + col) =
                        make_float2(acc[mt][nt][2], acc[mt][nt][3]);
                }
        }
    }
    gridbar(3 * NB);

    // ===================== P3: finalize (full-grid parallel) =====================
    {
        float lm = *lmbda;
        float sc = *scale;
        for (int b = bid; b < Bb; b += NB) {
            if (tid < 250) {
                int c = tid * 4;
                float4 s = make_float4(0.f, 0.f, 0.f, 0.f);
#pragma unroll
                for (int z = 0; z < KS; z++) {
                    float4 p = __ldcg(reinterpret_cast<const float4*>(
                        g_part + ((size_t)z * Bb + b) * Dd + c));
                    s.x += p.x; s.y += p.y; s.z += p.z; s.w += p.w;
                }
                float4 qc = __ldcg(reinterpret_cast<const float4*>(g_q + c));
                float4 bdc = *reinterpret_cast<const float4*>(g_bd + c);
                float qb = __ldcg(g_q + Cc + b);
                float bdb = g_bd[Cc + b];
                float4 o;
                {
                    float quad = qb + qc.x - 2.f * s.x;
                    float bd = bdb - bdc.x;
                    o.x = -sc * (sqrtf(quad + 1e-6f) + lm * sqrtf(bd * bd + 1e-6f));
                }
                {
                    float quad = qb + qc.y - 2.f * s.y;
                    float bd = bdb - bdc.y;
                    o.y = -sc * (sqrtf(quad + 1e-6f) + lm * sqrtf(bd * bd + 1e-6f));
                }
                {
                    float quad = qb + qc.z - 2.f * s.z;
                    float bd = bdb - bdc.z;
                    o.z = -sc * (sqrtf(quad + 1e-6f) + lm * sqrtf(bd * bd + 1e-6f));
                }
                {
                    float quad = qb + qc.w - 2.f * s.w;
                    float bd = bdb - bdc.w;
                    o.w = -sc * (sqrtf(quad + 1e-6f) + lm * sqrtf(bd * bd + 1e-6f));
                }
                *reinterpret_cast<float4*>(out + (size_t)b * Cc + c) = o;
            }
        }
    }

    // ---- final arrival: last block resets the barrier counter (replay-safe) ----
    __syncthreads();
    if (tid == 0) {
        int t = atomicAdd(&g_barCnt, 1);
        if (t == 4 * NB - 1) *(volatile int*)&g_barCnt = 0;
    }
}

// ---------------------------------------------------------------------------
extern "C" void kernel_launch(void* const* d_in, const int* in_sizes, int n_in,
                              void* d_out, int out_size) {
    const float *x = nullptr, *mu = nullptr, *beta = nullptr, *L = nullptr;
    const float *lmbda = nullptr, *scale = nullptr;
    for (int i = 0; i < n_in; i++) {
        const float* p = (const float*)d_in[i];
        switch (in_sizes[i]) {
            case Bb * Dd:  x = p; break;
            case Cc * Dd:  mu = p; break;
            case Dd:       beta = p; break;
            case Dd * Dd:  L = p; break;
            case 1:        if (!lmbda) lmbda = p; else scale = p; break;
            default: break;
        }
    }

    mega<<<NB, 256>>>(x, mu, beta, L, lmbda, scale, (float*)d_out);
}